// round 12
// baseline (speedup 1.0000x reference)
#include <cuda_runtime.h>
#include <cuda_bf16.h>
#include <cstdint>

// FilterLayer: y[b,c,h,w] = sum_{di,dj in 5x5} f[b, di*5+dj, h, w] * xpad[b, c, h+di, w+dj]
// x: [4,3,512,512] f32, f: [4,25,512,512] f32, out: [4,3,512,512] f32, zero pad p=2.
//
// R9: full-depth async prefetch of f. At block start, ALL 25 planes x 4 rows
// (50 KB) are issued as 100 cp.async.bulk 512B copies with one mbarrier per
// di-stage (5 planes / 10 KB each). Main loop has NO __syncthreads and NO
// refill: each warp waits each stage's mbarrier (parity 0) and consumes via
// conflict-free LDS.128. This keeps a ~50KB/block DRAM request queue on the
// async proxy, bypassing the per-SM L1tex outstanding-miss cap that pinned
// all LDG variants at ~62% DRAM. x stays on the LDG/L1 path (25x reuse).

#define WIN 5
#define CH 3
#define TROWS 4
#define TCOLS 128
#define PLANE_BYTES (TROWS * TCOLS * 4)          // 2048 per plane per block
#define STAGE_BYTES (WIN * PLANE_BYTES)          // 10240 per di-stage
#define F_BYTES (WIN * STAGE_BYTES)              // 51200 per block
#define SF_OFF 64                                 // mbarriers live below
#define SMEM_TOTAL (SF_OFF + F_BYTES)

__device__ __forceinline__ uint32_t smem_u32(const void* p) {
    uint32_t a;
    asm("{ .reg .u64 t; cvta.to.shared.u64 t, %1; cvt.u32.u64 %0, t; }"
        : "=r"(a) : "l"(p));
    return a;
}
__device__ __forceinline__ void mbar_init(uint32_t mbar, uint32_t count) {
    asm volatile("mbarrier.init.shared.b64 [%0], %1;" :: "r"(mbar), "r"(count) : "memory");
}
__device__ __forceinline__ void mbar_expect_tx(uint32_t mbar, uint32_t bytes) {
    asm volatile("mbarrier.arrive.expect_tx.shared.b64 _, [%0], %1;"
                 :: "r"(mbar), "r"(bytes) : "memory");
}
__device__ __forceinline__ void mbar_wait0(uint32_t mbar) {
    uint32_t done;
    asm volatile(
        "{\n\t.reg .pred p;\n\t"
        "mbarrier.try_wait.parity.acquire.cta.shared::cta.b64 p, [%1], 0;\n\t"
        "selp.b32 %0, 1, 0, p;\n\t}"
        : "=r"(done) : "r"(mbar) : "memory");
    if (!done) {
        asm volatile(
            "{\n\t.reg .pred P1;\n\t"
            "W_%=:\n\t"
            "mbarrier.try_wait.parity.acquire.cta.shared::cta.b64 P1, [%0], 0, 0x989680;\n\t"
            "@P1 bra.uni D_%=;\n\t"
            "bra.uni W_%=;\n\t"
            "D_%=:\n\t}"
            :: "r"(mbar) : "memory");
    }
}
__device__ __forceinline__ void bulk_copy_512(uint32_t dst_smem, const void* src, uint32_t mbar) {
    asm volatile(
        "cp.async.bulk.shared::cluster.global.mbarrier::complete_tx::bytes "
        "[%0], [%1], 512, [%2];"
        :: "r"(dst_smem), "l"(src), "r"(mbar) : "memory");
}

__global__ __launch_bounds__(128)
void FilterLayer_4664334483556_kernel(const float* __restrict__ x,
                                      const float* __restrict__ f,
                                      float* __restrict__ out)
{
    extern __shared__ __align__(128) char smem[];
    const uint32_t smem_base = smem_u32(smem);
    const uint32_t sf_base   = smem_base + SF_OFF;

    const int H = 512, W = 512;
    const int tx = threadIdx.x;              // 0..31
    const int ty = threadIdx.y;              // 0..3
    const int tid = ty * 32 + tx;
    const int b  = blockIdx.z;
    const int h0 = blockIdx.y * TROWS;
    const int w0 = blockIdx.x * TCOLS;
    const int h  = h0 + ty;
    const int wb = w0 + tx * 4;

    const size_t HW = (size_t)H * W;
    const float* fblk = f + ((size_t)b * (WIN * WIN)) * HW + (size_t)h0 * W + w0;

    // ---- init 5 stage mbarriers, then launch the full 50KB prefetch ----
    if (tid == 0) {
        #pragma unroll
        for (int s = 0; s < WIN; s++)
            mbar_init(smem_base + s * 8, 1);
    }
    __syncthreads();

    if (tid == 0) {
        #pragma unroll
        for (int s = 0; s < WIN; s++)
            mbar_expect_tx(smem_base + s * 8, STAGE_BYTES);
    }
    if (tid < WIN * WIN * TROWS) {           // 100 copies of 512 B
        const int s   = tid / (WIN * TROWS);         // di-stage
        const int rem = tid - s * (WIN * TROWS);
        const int dj  = rem >> 2;
        const int r   = rem & 3;
        const int k   = s * WIN + dj;
        const float* src = fblk + (size_t)k * HW + (size_t)r * W;
        const uint32_t dst = sf_base + (uint32_t)(k * PLANE_BYTES + r * 512);
        bulk_copy_512(dst, src, smem_base + s * 8);
    }

    const bool leftOK  = (wb >= 4);
    const bool rightOK = (wb <= W - 8);

    float acc[CH][4];
    #pragma unroll
    for (int c = 0; c < CH; c++)
        #pragma unroll
        for (int q = 0; q < 4; q++)
            acc[c][q] = 0.0f;

    const float* xbase = x + (size_t)b * CH * HW + wb;

    #pragma unroll
    for (int di = 0; di < WIN; di++) {
        mbar_wait0(smem_base + di * 8);      // stage arrival; no block barrier

        // 5 filter vectors for this stage: LDS.128, tx*16B -> conflict-free
        float4 fv[WIN];
        #pragma unroll
        for (int dj = 0; dj < WIN; dj++) {
            const uint32_t a = sf_base
                + (uint32_t)((di * WIN + dj) * PLANE_BYTES + ty * 512 + tx * 16);
            asm volatile("ld.shared.v4.f32 {%0,%1,%2,%3}, [%4];"
                         : "=f"(fv[dj].x), "=f"(fv[dj].y),
                           "=f"(fv[dj].z), "=f"(fv[dj].w)
                         : "r"(a));
        }

        const int gh = h + di - 2;
        const bool rv = ((unsigned)gh < (unsigned)H);

        #pragma unroll
        for (int c = 0; c < CH; c++) {
            const float* row = xbase + ((size_t)c * H + gh) * W;
            float4 v0 = make_float4(0.f, 0.f, 0.f, 0.f);
            float4 v1 = make_float4(0.f, 0.f, 0.f, 0.f);
            float4 v2 = make_float4(0.f, 0.f, 0.f, 0.f);
            if (rv) {
                if (leftOK)  v0 = *reinterpret_cast<const float4*>(row - 4);
                             v1 = *reinterpret_cast<const float4*>(row);
                if (rightOK) v2 = *reinterpret_cast<const float4*>(row + 4);
            }
            float xr[8];
            xr[0] = v0.z; xr[1] = v0.w;
            xr[2] = v1.x; xr[3] = v1.y; xr[4] = v1.z; xr[5] = v1.w;
            xr[6] = v2.x; xr[7] = v2.y;

            #pragma unroll
            for (int dj = 0; dj < WIN; dj++) {
                acc[c][0] = fmaf(fv[dj].x, xr[dj + 0], acc[c][0]);
                acc[c][1] = fmaf(fv[dj].y, xr[dj + 1], acc[c][1]);
                acc[c][2] = fmaf(fv[dj].z, xr[dj + 2], acc[c][2]);
                acc[c][3] = fmaf(fv[dj].w, xr[dj + 3], acc[c][3]);
            }
        }
    }

    float* ob = out + (size_t)b * CH * HW + (size_t)h * W + wb;
    #pragma unroll
    for (int c = 0; c < CH; c++) {
        float4 v = make_float4(acc[c][0], acc[c][1], acc[c][2], acc[c][3]);
        *reinterpret_cast<float4*>(ob + c * HW) = v;
    }
}

extern "C" void kernel_launch(void* const* d_in, const int* in_sizes, int n_in,
                              void* d_out, int out_size)
{
    const float* x = (const float*)d_in[0];
    const float* f = (const float*)d_in[1];
    float* out = (float*)d_out;

    cudaFuncSetAttribute(FilterLayer_4664334483556_kernel,
                         cudaFuncAttributeMaxDynamicSharedMemorySize, SMEM_TOTAL);

    dim3 block(32, 4, 1);
    dim3 grid(4, 128, 4);   // (512/128, 512/4, 4) = 2048 blocks
    FilterLayer_4664334483556_kernel<<<grid, block, SMEM_TOTAL>>>(x, f, out);
}

// round 13
// speedup vs baseline: 1.2859x; 1.2859x over previous
#include <cuda_runtime.h>
#include <cuda_bf16.h>
#include <cstdint>

// FilterLayer: y[b,c,h,w] = sum_{di,dj in 5x5} f[b, di*5+dj, h, w] * xpad[b, c, h+di, w+dj]
// x: [4,3,512,512] f32, f: [4,25,512,512] f32, out: [4,3,512,512] f32, zero pad p=2.
//
// R12 = R2 (best: 4px/thread, 256-thr blocks, 64 regs, occ 40%) + fire-and-forget
// L2 prefetch of the block's full f footprint (25 planes x 8 rows x 512B = 100KB)
// via cp.async.bulk.prefetch.L2.global. Prefetches carry no destination, use no
// L1tex MSHR slots, and queue arbitrarily deep -> they stream DRAM at engine
// depth while the demand __ldcg loads hit L2 (~234cyc instead of ~600cyc),
// roughly doubling the demand bandwidth sustainable under the per-SM
// outstanding-miss cap that pinned every earlier variant at ~5 TB/s.

#define WIN 5
#define CH 3

__device__ __forceinline__ void l2_prefetch_512(const void* src) {
    asm volatile("cp.async.bulk.prefetch.L2.global [%0], 512;"
                 :: "l"(src) : "memory");
}

__global__ __launch_bounds__(256, 4)
void FilterLayer_4664334483556_kernel(const float* __restrict__ x,
                                      const float* __restrict__ f,
                                      float* __restrict__ out)
{
    const int H = 512, W = 512;
    const int tx = threadIdx.x;              // 0..31
    const int ty = threadIdx.y;              // 0..7
    const int tid = ty * 32 + tx;
    const int b  = blockIdx.z;
    const int h0 = blockIdx.y * 8;
    const int h  = h0 + ty;                  // output row
    const int w0 = blockIdx.x * 128;
    const int wb = w0 + tx * 4;              // first of 4 output cols

    const size_t HW = (size_t)H * W;

    // ---- fire-and-forget L2 prefetch of this block's f footprint ----
    // 25 planes x 8 rows x 512 B, one 512B prefetch per thread (tid 0..199).
    {
        const float* fblk = f + ((size_t)b * (WIN * WIN)) * HW + (size_t)h0 * W + w0;
        if (tid < WIN * WIN * 8) {
            const int k = tid >> 3;          // plane 0..24
            const int r = tid & 7;           // row within tile 0..7
            l2_prefetch_512(fblk + (size_t)k * HW + (size_t)r * W);
        }
    }

    const bool leftOK  = (wb >= 4);
    const bool rightOK = (wb <= W - 8);

    float acc[CH][4];
    #pragma unroll
    for (int c = 0; c < CH; c++)
        #pragma unroll
        for (int q = 0; q < 4; q++)
            acc[c][q] = 0.0f;

    const float* fbase = f + ((size_t)b * (WIN * WIN)) * HW + (size_t)h * W + wb;
    const float* xbase = x + (size_t)b * CH * HW + wb;

    #pragma unroll
    for (int di = 0; di < WIN; di++) {
        const int gh = h + di - 2;
        const bool rv = ((unsigned)gh < (unsigned)H);

        // ---- filter row: 5 x LDG.128 via L2 (hits prefetched lines) ----
        float4 fv[WIN];
        #pragma unroll
        for (int dj = 0; dj < WIN; dj++)
            fv[dj] = __ldcg(reinterpret_cast<const float4*>(
                         fbase + (size_t)(di * WIN + dj) * HW));

        #pragma unroll
        for (int c = 0; c < CH; c++) {
            const float* row = xbase + ((size_t)c * H + gh) * W;

            float4 v0 = make_float4(0.f, 0.f, 0.f, 0.f);
            float4 v1 = make_float4(0.f, 0.f, 0.f, 0.f);
            float4 v2 = make_float4(0.f, 0.f, 0.f, 0.f);
            if (rv) {
                if (leftOK)  v0 = __ldca(reinterpret_cast<const float4*>(row - 4));
                             v1 = __ldca(reinterpret_cast<const float4*>(row));
                if (rightOK) v2 = __ldca(reinterpret_cast<const float4*>(row + 4));
            }

            float xr[8];
            xr[0] = v0.z; xr[1] = v0.w;
            xr[2] = v1.x; xr[3] = v1.y; xr[4] = v1.z; xr[5] = v1.w;
            xr[6] = v2.x; xr[7] = v2.y;

            #pragma unroll
            for (int dj = 0; dj < WIN; dj++) {
                acc[c][0] = fmaf(fv[dj].x, xr[dj + 0], acc[c][0]);
                acc[c][1] = fmaf(fv[dj].y, xr[dj + 1], acc[c][1]);
                acc[c][2] = fmaf(fv[dj].z, xr[dj + 2], acc[c][2]);
                acc[c][3] = fmaf(fv[dj].w, xr[dj + 3], acc[c][3]);
            }
        }
    }

    float* ob = out + (size_t)b * CH * HW + (size_t)h * W + wb;
    #pragma unroll
    for (int c = 0; c < CH; c++) {
        float4 v = make_float4(acc[c][0], acc[c][1], acc[c][2], acc[c][3]);
        *reinterpret_cast<float4*>(ob + c * HW) = v;
    }
}

extern "C" void kernel_launch(void* const* d_in, const int* in_sizes, int n_in,
                              void* d_out, int out_size)
{
    const float* x = (const float*)d_in[0];
    const float* f = (const float*)d_in[1];
    float* out = (float*)d_out;

    dim3 block(32, 8, 1);
    dim3 grid(4, 64, 4);   // (512/128, 512/8, 4) = 1024 blocks
    FilterLayer_4664334483556_kernel<<<grid, block>>>(x, f, out);
}